// round 6
// baseline (speedup 1.0000x reference)
#include <cuda_runtime.h>

#define NN 50000
#define NE 500000
#define HH 128
typedef unsigned long long ull;

// Scratch (device globals — allocation-free rule)
__device__ float g_agg[NN * 512];            // aggregated raw neighbor features
__device__ ull g_Wt2[4 * HH * HH];           // weights, transposed + pair-duplicated
                                             // m: 0=W_s_root 1=W_s_rel 2=W_v_root 3=W_v_rel
__device__ int g_is64;                       // edge_index dtype flag
__device__ int g_deg[NN];
__device__ int g_cur[NN];
__device__ int g_off[NN + 1];
__device__ int g_ecol[NE];

__device__ __forceinline__ int clampn(int v) {
    return (v < 0) ? 0 : ((v >= NN) ? NN - 1 : v);
}

// ---------------------------------------------------------------------------
// Merged setup: zero counters, probe dtype, transpose + pair-duplicate weights.
// W layout: g_Wt2[(m<<14) + (k<<7) + col(o)] = {W[o][k], W[o][k]} where
// col(o) = ((((o>>1)&3)*16 + (o>>3)) << 1) | (o&1)  — so the GEMM inner loop
// reads pairs (o=ox*8+2i, ox*8+2i+1) at slot (i*16+ox) with conflict-free LDS.128.
__global__ void setup_kernel(const int* __restrict__ ei32,
                             const float* __restrict__ Wsroot,
                             const float* __restrict__ Wsrel,
                             const float* __restrict__ Wvroot,
                             const float* __restrict__ Wvrel) {
    int i = blockIdx.x * blockDim.x + threadIdx.x;
    if (i < NN) { g_deg[i] = 0; g_cur[i] = 0; }
    if (i == 0) {
        int all_zero = 1;
        #pragma unroll
        for (int q = 0; q < 32; q++)
            if (ei32[2 * q + 1] != 0) all_zero = 0;
        g_is64 = all_zero;
    }
    if (i < 4 * HH * HH) {
        int m = i >> 14;
        int rest = i & (HH * HH - 1);
        int o = rest >> 7;
        int k = rest & 127;
        const float* src = (m == 0) ? Wsroot : (m == 1) ? Wsrel : (m == 2) ? Wvroot : Wvrel;
        float v = src[(o << 7) + k];
        ull d;
        asm("mov.b64 %0, {%1, %1};" : "=l"(d) : "f"(v));
        int col = ((((o >> 1) & 3) * 16 + (o >> 3)) << 1) | (o & 1);
        g_Wt2[(m << 14) + (k << 7) + col] = d;
    }
}

// ---------------------------------------------------------------------------
// CSR build: histogram -> exclusive scan -> scatter (indices clamped).
__global__ void hist_kernel(const void* __restrict__ ei_raw) {
    int e = blockIdx.x * blockDim.x + threadIdx.x;
    if (e >= NE) return;
    int r = g_is64 ? (int)((const long long*)ei_raw)[e]
                   : ((const int*)ei_raw)[e];
    atomicAdd(&g_deg[clampn(r)], 1);
}

__global__ void scan_kernel() {
    __shared__ int sm[1024];
    int t = threadIdx.x;
    const int CH = (NN + 1023) / 1024;   // 49
    int b = t * CH;
    int e = min(b + CH, NN);
    int s = 0;
    for (int i = b; i < e; i++) s += g_deg[i];
    sm[t] = s;
    __syncthreads();
    for (int o = 1; o < 1024; o <<= 1) {
        int v = (t >= o) ? sm[t - o] : 0;
        __syncthreads();
        sm[t] += v;
        __syncthreads();
    }
    int run = (t == 0) ? 0 : sm[t - 1];
    for (int i = b; i < e; i++) { g_off[i] = run; run += g_deg[i]; }
    if (t == 1023) g_off[NN] = sm[1023];
}

__global__ void scatter_kernel(const void* __restrict__ ei_raw) {
    int e = blockIdx.x * blockDim.x + threadIdx.x;
    if (e >= NE) return;
    int r, c;
    if (g_is64) {
        const long long* ei = (const long long*)ei_raw;
        r = (int)ei[e];
        c = (int)ei[NE + e];
    } else {
        const int* ei = (const int*)ei_raw;
        r = ei[e];
        c = ei[NE + e];
    }
    r = clampn(r);
    c = clampn(c);
    int p = atomicAdd(&g_cur[r], 1);
    int slot = g_off[r] + p;
    if (slot >= NE) slot = NE - 1;
    g_ecol[slot] = c;
}

// ---------------------------------------------------------------------------
// Atomic-free gather aggregation (unchanged from R5 — proven).
#define GW 8
__global__ void gather_kernel(const float4* __restrict__ x4) {
    int w = threadIdx.x >> 5, lane = threadIdx.x & 31;
    const int ngb = NN / GW;            // 6250
    int bid = blockIdx.x;
    int pass = bid / ngb;
    int n = (bid - pass * ngb) * GW + w;
    int beg = g_off[n], end = g_off[n + 1];
    if (beg < 0) beg = 0;
    if (end > NE) end = NE;
    int jo = (pass << 5) + lane;

    float4 a0 = make_float4(0.f, 0.f, 0.f, 0.f);
    float4 a1 = a0;
    int i = beg;
    for (; i + 2 <= end; i += 2) {
        int c0 = g_ecol[i];
        int c1 = g_ecol[i + 1];
        float4 v0 = x4[(size_t)c0 * 128 + jo];
        float4 v1 = x4[(size_t)c1 * 128 + jo];
        a0.x += v0.x; a0.y += v0.y; a0.z += v0.z; a0.w += v0.w;
        a1.x += v1.x; a1.y += v1.y; a1.z += v1.z; a1.w += v1.w;
    }
    if (i < end) {
        int c0 = g_ecol[i];
        float4 v0 = x4[(size_t)c0 * 128 + jo];
        a0.x += v0.x; a0.y += v0.y; a0.z += v0.z; a0.w += v0.w;
    }
    float4 r = make_float4(a0.x + a1.x, a0.y + a1.y, a0.z + a1.z, a0.w + a1.w);
    ((float4*)g_agg)[(size_t)n * 128 + jo] = r;
}

// ---------------------------------------------------------------------------
// Fused GEMM: out_row = x_row @ Wroot^T + agg_row @ Wrel^T (+ b for scalar).
// Block: 128 rows x 128 outputs, 256 threads. Thread = 4 row-pairs x 8 outputs.
// Weights pre-duplicated {w,w} -> zero packing movs in inner loop.
__device__ __forceinline__ int rowbase(int is_s, int r, int mlim) {
    r = (r < mlim) ? r : (mlim - 1);
    if (is_s) return r << 9;
    int n = r / 3;
    int ch = r - n * 3;
    return (n << 9) + ((ch + 1) << 7);
}

#define TM 128
#define KT 32

__global__ __launch_bounds__(256, 2)
void gemm_kernel(const float* __restrict__ x,
                 const float* __restrict__ b_s,
                 float* __restrict__ out,
                 int nb_s) {
    __shared__ __align__(16) float As[KT][TM + 2];   // k-major
    __shared__ __align__(16) ull Wsm[KT][HH];        // [k][slot*2+b], pair-dup

    int t = threadIdx.x;
    int bid = (int)blockIdx.x;
    int is_s = (bid < nb_s) ? 1 : 0;
    int row0 = (is_s ? bid : bid - nb_s) * TM;
    int mlim = is_s ? NN : 3 * NN;
    const ull* Wroot = g_Wt2 + (is_s ? 0 : 2 * HH * HH);
    const ull* Wrel  = g_Wt2 + (is_s ? HH * HH : 3 * HH * HH);

    int ox = t & 15;        // output octet: outputs ox*8 .. ox*8+7
    int ry = t >> 4;        // row octet: rows ry*8 .. ry*8+7

    // A loader: thread -> row t>>1, k-half (t&1)*16
    int alr = t >> 1;
    int akh = (t & 1) << 4;
    int ab = rowbase(is_s, row0 + alr, mlim);

    ull acc[4][8];
    #pragma unroll
    for (int p = 0; p < 4; p++)
        #pragma unroll
        for (int j = 0; j < 8; j++) acc[p][j] = 0ULL;

    #pragma unroll 1
    for (int half = 0; half < 2; half++) {
        const float* A = half ? g_agg : x;
        const ull* W = half ? Wrel : Wroot;
        #pragma unroll 1
        for (int kc = 0; kc < HH; kc += KT) {
            __syncthreads();
            // A tile: 128 rows x 32 k, stored k-major. 16 floats per thread.
            #pragma unroll
            for (int q4 = 0; q4 < 4; q4++) {
                float4 a = *(const float4*)(A + ab + kc + akh + q4 * 4);
                As[akh + q4 * 4 + 0][alr] = a.x;
                As[akh + q4 * 4 + 1][alr] = a.y;
                As[akh + q4 * 4 + 2][alr] = a.z;
                As[akh + q4 * 4 + 3][alr] = a.w;
            }
            // W tile: straight ull2 copy of 32 k-rows x 128 ull
            {
                const ulonglong2* wsrc = (const ulonglong2*)(W + (size_t)kc * HH);
                ulonglong2* wdst = (ulonglong2*)&Wsm[0][0];
                #pragma unroll
                for (int u = 0; u < 8; u++)
                    wdst[t + 256 * u] = wsrc[t + 256 * u];
            }
            __syncthreads();

            #pragma unroll
            for (int k = 0; k < KT; k++) {
                ull ap[4];
                #pragma unroll
                for (int p = 0; p < 4; p++)
                    ap[p] = *(const ull*)(&As[k][ry * 8 + 2 * p]);
                ulonglong2 wv[4];
                #pragma unroll
                for (int i = 0; i < 4; i++)
                    wv[i] = *(const ulonglong2*)(&Wsm[k][(i * 16 + ox) * 2]);
                #pragma unroll
                for (int i = 0; i < 4; i++) {
                    #pragma unroll
                    for (int p = 0; p < 4; p++) {
                        asm("fma.rn.f32x2 %0, %1, %2, %0;"
                            : "+l"(acc[p][2 * i]) : "l"(ap[p]), "l"(wv[i].x));
                        asm("fma.rn.f32x2 %0, %1, %2, %0;"
                            : "+l"(acc[p][2 * i + 1]) : "l"(ap[p]), "l"(wv[i].y));
                    }
                }
            }
        }
    }

    float bv[8];
    #pragma unroll
    for (int j = 0; j < 8; j++) bv[j] = 0.f;
    if (is_s) {
        float4 b0 = *(const float4*)(b_s + ox * 8);
        float4 b1 = *(const float4*)(b_s + ox * 8 + 4);
        bv[0] = b0.x; bv[1] = b0.y; bv[2] = b0.z; bv[3] = b0.w;
        bv[4] = b1.x; bv[5] = b1.y; bv[6] = b1.z; bv[7] = b1.w;
    }

    #pragma unroll
    for (int p = 0; p < 4; p++) {
        int ra = row0 + ry * 8 + 2 * p;
        int rb = ra + 1;
        float lo[8], hi[8];
        #pragma unroll
        for (int j = 0; j < 8; j++)
            asm("mov.b64 {%0,%1}, %2;" : "=f"(lo[j]), "=f"(hi[j]) : "l"(acc[p][j]));
        if (ra < mlim) {
            float* dst = out + rowbase(is_s, ra, mlim) + ox * 8;
            *(float4*)(dst)     = make_float4(lo[0] + bv[0], lo[1] + bv[1], lo[2] + bv[2], lo[3] + bv[3]);
            *(float4*)(dst + 4) = make_float4(lo[4] + bv[4], lo[5] + bv[5], lo[6] + bv[6], lo[7] + bv[7]);
        }
        if (rb < mlim) {
            float* dst = out + rowbase(is_s, rb, mlim) + ox * 8;
            *(float4*)(dst)     = make_float4(hi[0] + bv[0], hi[1] + bv[1], hi[2] + bv[2], hi[3] + bv[3]);
            *(float4*)(dst + 4) = make_float4(hi[4] + bv[4], hi[5] + bv[5], hi[6] + bv[6], hi[7] + bv[7]);
        }
    }
}

// ---------------------------------------------------------------------------
extern "C" void kernel_launch(void* const* d_in, const int* in_sizes, int n_in,
                              void* d_out, int out_size) {
    const float* x      = (const float*)d_in[0];
    const void*  ei     = d_in[1];
    const float* Wsrel  = (const float*)d_in[2];
    const float* Wsroot = (const float*)d_in[3];
    const float* bsroot = (const float*)d_in[4];
    const float* Wvrel  = (const float*)d_in[5];
    const float* Wvroot = (const float*)d_in[6];
    float* out = (float*)d_out;

    setup_kernel<<<(4 * HH * HH + 255) / 256, 256>>>((const int*)ei, Wsroot, Wsrel, Wvroot, Wvrel);

    hist_kernel<<<(NE + 255) / 256, 256>>>(ei);
    scan_kernel<<<1, 1024>>>();
    scatter_kernel<<<(NE + 255) / 256, 256>>>(ei);

    gather_kernel<<<4 * (NN / GW), 256>>>((const float4*)x);

    int nb_s = (NN + TM - 1) / TM;            // 391
    int nb_v = (3 * NN + TM - 1) / TM;        // 1172
    gemm_kernel<<<nb_s + nb_v, 256>>>(x, bsroot, out, nb_s);
}

// round 8
// speedup vs baseline: 1.0807x; 1.0807x over previous
#include <cuda_runtime.h>

#define NN 50000
#define NE 500000
#define HH 128
typedef unsigned long long ull;

// Scratch (device globals — allocation-free rule)
__device__ float g_agg[NN * 512];            // aggregated raw neighbor features
__device__ float g_Wt[4 * HH * HH];          // weights transposed [m][k][o]
                                             // m: 0=W_s_root 1=W_s_rel 2=W_v_root 3=W_v_rel
__device__ int g_is64;                       // edge_index dtype flag
__device__ int g_deg[NN];
__device__ int g_cur[NN];
__device__ int g_off[NN + 1];
__device__ int g_ecol[NE];

__device__ __forceinline__ int clampn(int v) {
    return (v < 0) ? 0 : ((v >= NN) ? NN - 1 : v);
}

// ---------------------------------------------------------------------------
// Merged setup: zero counters, probe dtype, transpose weights.
__global__ void setup_kernel(const int* __restrict__ ei32,
                             const float* __restrict__ Wsroot,
                             const float* __restrict__ Wsrel,
                             const float* __restrict__ Wvroot,
                             const float* __restrict__ Wvrel) {
    int i = blockIdx.x * blockDim.x + threadIdx.x;
    if (i < NN) { g_deg[i] = 0; g_cur[i] = 0; }
    if (i == 0) {
        int all_zero = 1;
        #pragma unroll
        for (int q = 0; q < 32; q++)
            if (ei32[2 * q + 1] != 0) all_zero = 0;
        g_is64 = all_zero;
    }
    if (i < 4 * HH * HH) {
        int m = i >> 14;
        int rest = i & (HH * HH - 1);
        int o = rest >> 7;
        int k = rest & 127;
        const float* src = (m == 0) ? Wsroot : (m == 1) ? Wsrel : (m == 2) ? Wvroot : Wvrel;
        g_Wt[(m << 14) + (k << 7) + o] = src[(o << 7) + k];
    }
}

// ---------------------------------------------------------------------------
// CSR build: histogram -> exclusive scan -> scatter (indices clamped).
__global__ void hist_kernel(const void* __restrict__ ei_raw) {
    int e = blockIdx.x * blockDim.x + threadIdx.x;
    if (e >= NE) return;
    int r = g_is64 ? (int)((const long long*)ei_raw)[e]
                   : ((const int*)ei_raw)[e];
    atomicAdd(&g_deg[clampn(r)], 1);
}

__global__ void scan_kernel() {
    __shared__ int sm[1024];
    int t = threadIdx.x;
    const int CH = (NN + 1023) / 1024;   // 49
    int b = t * CH;
    int e = min(b + CH, NN);
    int s = 0;
    for (int i = b; i < e; i++) s += g_deg[i];
    sm[t] = s;
    __syncthreads();
    for (int o = 1; o < 1024; o <<= 1) {
        int v = (t >= o) ? sm[t - o] : 0;
        __syncthreads();
        sm[t] += v;
        __syncthreads();
    }
    int run = (t == 0) ? 0 : sm[t - 1];
    for (int i = b; i < e; i++) { g_off[i] = run; run += g_deg[i]; }
    if (t == 1023) g_off[NN] = sm[1023];
}

__global__ void scatter_kernel(const void* __restrict__ ei_raw) {
    int e = blockIdx.x * blockDim.x + threadIdx.x;
    if (e >= NE) return;
    int r, c;
    if (g_is64) {
        const long long* ei = (const long long*)ei_raw;
        r = (int)ei[e];
        c = (int)ei[NE + e];
    } else {
        const int* ei = (const int*)ei_raw;
        r = ei[e];
        c = ei[NE + e];
    }
    r = clampn(r);
    c = clampn(c);
    int p = atomicAdd(&g_cur[r], 1);
    int slot = g_off[r] + p;
    if (slot >= NE) slot = NE - 1;
    g_ecol[slot] = c;
}

// ---------------------------------------------------------------------------
// Atomic-free gather aggregation (unchanged — proven).
#define GW 8
__global__ void gather_kernel(const float4* __restrict__ x4) {
    int w = threadIdx.x >> 5, lane = threadIdx.x & 31;
    const int ngb = NN / GW;            // 6250
    int bid = blockIdx.x;
    int pass = bid / ngb;
    int n = (bid - pass * ngb) * GW + w;
    int beg = g_off[n], end = g_off[n + 1];
    if (beg < 0) beg = 0;
    if (end > NE) end = NE;
    int jo = (pass << 5) + lane;

    float4 a0 = make_float4(0.f, 0.f, 0.f, 0.f);
    float4 a1 = a0;
    int i = beg;
    for (; i + 2 <= end; i += 2) {
        int c0 = g_ecol[i];
        int c1 = g_ecol[i + 1];
        float4 v0 = x4[(size_t)c0 * 128 + jo];
        float4 v1 = x4[(size_t)c1 * 128 + jo];
        a0.x += v0.x; a0.y += v0.y; a0.z += v0.z; a0.w += v0.w;
        a1.x += v1.x; a1.y += v1.y; a1.z += v1.z; a1.w += v1.w;
    }
    if (i < end) {
        int c0 = g_ecol[i];
        float4 v0 = x4[(size_t)c0 * 128 + jo];
        a0.x += v0.x; a0.y += v0.y; a0.z += v0.z; a0.w += v0.w;
    }
    float4 r = make_float4(a0.x + a1.x, a0.y + a1.y, a0.z + a1.z, a0.w + a1.w);
    ((float4*)g_agg)[(size_t)n * 128 + jo] = r;
}

// ---------------------------------------------------------------------------
// Fused GEMM: out_row = x_row @ Wroot^T + agg_row @ Wrel^T (+ b for scalar).
// Block: 128 rows x 128 outputs, 256 threads. Thread = 4 row-pairs x 8 outputs.
// W stored plain float in smem (crossbar-cheap); duplicated per-use via movs.
// A read as 2 broadcast LDS.128 per k. As row stride = TM+4 floats (528 B,
// 16B-multiple) so the LDS.128 reads stay aligned for every k.
__device__ __forceinline__ int rowbase(int is_s, int r, int mlim) {
    r = (r < mlim) ? r : (mlim - 1);
    if (is_s) return r << 9;
    int n = r / 3;
    int ch = r - n * 3;
    return (n << 9) + ((ch + 1) << 7);
}

#define TM 128
#define KT 32

__global__ __launch_bounds__(256, 2)
void gemm_kernel(const float* __restrict__ x,
                 const float* __restrict__ b_s,
                 float* __restrict__ out,
                 int nb_s) {
    __shared__ __align__(16) float As[KT][TM + 4];   // k-major; 528B stride (16B-aligned)
    __shared__ __align__(16) float Ws[KT][HH];       // [k][o]

    int t = threadIdx.x;
    int bid = (int)blockIdx.x;
    int is_s = (bid < nb_s) ? 1 : 0;
    int row0 = (is_s ? bid : bid - nb_s) * TM;
    int mlim = is_s ? NN : 3 * NN;
    const float* Wroot = g_Wt + (is_s ? 0 : 2 * HH * HH);
    const float* Wrel  = g_Wt + (is_s ? HH * HH : 3 * HH * HH);

    int ox = t & 15;        // output octet: outputs ox*8 .. ox*8+7
    int ry = t >> 4;        // row octet: rows ry*8 .. ry*8+7

    // A loader: thread -> row t>>1, k-half (t&1)*16
    int alr = t >> 1;
    int akh = (t & 1) << 4;
    int ab = rowbase(is_s, row0 + alr, mlim);
    // W loader: 32 k-rows x 128 floats = 16KB, thread copies 4 float4
    int wk = t >> 3;
    int wq = t & 7;

    ull acc[4][8];
    #pragma unroll
    for (int p = 0; p < 4; p++)
        #pragma unroll
        for (int j = 0; j < 8; j++) acc[p][j] = 0ULL;

    #pragma unroll 1
    for (int half = 0; half < 2; half++) {
        const float* A = half ? g_agg : x;
        const float* W = half ? Wrel : Wroot;
        #pragma unroll 1
        for (int kc = 0; kc < HH; kc += KT) {
            __syncthreads();
            // A tile: 128 rows x 32 k, stored k-major. 16 floats per thread.
            #pragma unroll
            for (int q4 = 0; q4 < 4; q4++) {
                float4 a = *(const float4*)(A + ab + kc + akh + q4 * 4);
                As[akh + q4 * 4 + 0][alr] = a.x;
                As[akh + q4 * 4 + 1][alr] = a.y;
                As[akh + q4 * 4 + 2][alr] = a.z;
                As[akh + q4 * 4 + 3][alr] = a.w;
            }
            // W tile copy (plain float, coalesced)
            {
                const float* wsrc = W + (size_t)(kc + wk) * HH;
                #pragma unroll
                for (int s = 0; s < 4; s++) {
                    float4 wv = *(const float4*)(wsrc + (wq + 8 * s) * 4);
                    *(float4*)(&Ws[wk][(wq + 8 * s) * 4]) = wv;
                }
            }
            __syncthreads();

            #pragma unroll
            for (int k = 0; k < KT; k++) {
                // 4 row-pairs via 2 broadcast LDS.128 (rows ry*8 .. ry*8+7)
                float4 a01 = *(const float4*)(&As[k][ry * 8]);
                float4 a23 = *(const float4*)(&As[k][ry * 8 + 4]);
                ull ap[4];
                asm("mov.b64 %0, {%1, %2};" : "=l"(ap[0]) : "f"(a01.x), "f"(a01.y));
                asm("mov.b64 %0, {%1, %2};" : "=l"(ap[1]) : "f"(a01.z), "f"(a01.w));
                asm("mov.b64 %0, {%1, %2};" : "=l"(ap[2]) : "f"(a23.x), "f"(a23.y));
                asm("mov.b64 %0, {%1, %2};" : "=l"(ap[3]) : "f"(a23.z), "f"(a23.w));
                float4 w0 = *(const float4*)(&Ws[k][ox * 8]);
                float4 w1 = *(const float4*)(&Ws[k][ox * 8 + 4]);
                #pragma unroll
                for (int j = 0; j < 8; j++) {
                    float wj = (j == 0) ? w0.x : (j == 1) ? w0.y : (j == 2) ? w0.z
                             : (j == 3) ? w0.w : (j == 4) ? w1.x : (j == 5) ? w1.y
                             : (j == 6) ? w1.z : w1.w;
                    ull wp;
                    asm("mov.b64 %0, {%1, %1};" : "=l"(wp) : "f"(wj));
                    #pragma unroll
                    for (int p = 0; p < 4; p++) {
                        asm("fma.rn.f32x2 %0, %1, %2, %0;"
                            : "+l"(acc[p][j]) : "l"(ap[p]), "l"(wp));
                    }
                }
            }
        }
    }

    float bv[8];
    #pragma unroll
    for (int j = 0; j < 8; j++) bv[j] = 0.f;
    if (is_s) {
        float4 b0 = *(const float4*)(b_s + ox * 8);
        float4 b1 = *(const float4*)(b_s + ox * 8 + 4);
        bv[0] = b0.x; bv[1] = b0.y; bv[2] = b0.z; bv[3] = b0.w;
        bv[4] = b1.x; bv[5] = b1.y; bv[6] = b1.z; bv[7] = b1.w;
    }

    #pragma unroll
    for (int p = 0; p < 4; p++) {
        int ra = row0 + ry * 8 + 2 * p;
        int rb = ra + 1;
        float lo[8], hi[8];
        #pragma unroll
        for (int j = 0; j < 8; j++)
            asm("mov.b64 {%0,%1}, %2;" : "=f"(lo[j]), "=f"(hi[j]) : "l"(acc[p][j]));
        if (ra < mlim) {
            float* dst = out + rowbase(is_s, ra, mlim) + ox * 8;
            *(float4*)(dst)     = make_float4(lo[0] + bv[0], lo[1] + bv[1], lo[2] + bv[2], lo[3] + bv[3]);
            *(float4*)(dst + 4) = make_float4(lo[4] + bv[4], lo[5] + bv[5], lo[6] + bv[6], lo[7] + bv[7]);
        }
        if (rb < mlim) {
            float* dst = out + rowbase(is_s, rb, mlim) + ox * 8;
            *(float4*)(dst)     = make_float4(hi[0] + bv[0], hi[1] + bv[1], hi[2] + bv[2], hi[3] + bv[3]);
            *(float4*)(dst + 4) = make_float4(hi[4] + bv[4], hi[5] + bv[5], hi[6] + bv[6], hi[7] + bv[7]);
        }
    }
}

// ---------------------------------------------------------------------------
extern "C" void kernel_launch(void* const* d_in, const int* in_sizes, int n_in,
                              void* d_out, int out_size) {
    const float* x      = (const float*)d_in[0];
    const void*  ei     = d_in[1];
    const float* Wsrel  = (const float*)d_in[2];
    const float* Wsroot = (const float*)d_in[3];
    const float* bsroot = (const float*)d_in[4];
    const float* Wvrel  = (const float*)d_in[5];
    const float* Wvroot = (const float*)d_in[6];
    float* out = (float*)d_out;

    setup_kernel<<<(4 * HH * HH + 255) / 256, 256>>>((const int*)ei, Wsroot, Wsrel, Wvroot, Wvrel);

    hist_kernel<<<(NE + 255) / 256, 256>>>(ei);
    scan_kernel<<<1, 1024>>>();
    scatter_kernel<<<(NE + 255) / 256, 256>>>(ei);

    gather_kernel<<<4 * (NN / GW), 256>>>((const float4*)x);

    int nb_s = (NN + TM - 1) / TM;            // 391
    int nb_v = (3 * NN + TM - 1) / TM;        // 1172
    gemm_kernel<<<nb_s + nb_v, 256>>>(x, bsroot, out, nb_s);
}

// round 9
// speedup vs baseline: 1.1650x; 1.0781x over previous
#include <cuda_runtime.h>

#define NN 50000
#define NE 500000
#define HH 128
typedef unsigned long long ull;

// Scratch (device globals — allocation-free rule)
__device__ float g_agg[NN * 512];            // aggregated raw neighbor features
__device__ float g_Wt[4 * HH * HH];          // weights transposed [m][k][o]
                                             // m: 0=W_s_root 1=W_s_rel 2=W_v_root 3=W_v_rel
__device__ int g_is64;                       // edge_index dtype flag
__device__ int g_deg[NN];
__device__ int g_cur[NN];
__device__ int g_off[NN + 1];
__device__ int g_ecol[NE];

__device__ __forceinline__ int clampn(int v) {
    return (v < 0) ? 0 : ((v >= NN) ? NN - 1 : v);
}

// ---------------------------------------------------------------------------
// Merged setup: zero counters, probe dtype, transpose weights.
__global__ void setup_kernel(const int* __restrict__ ei32,
                             const float* __restrict__ Wsroot,
                             const float* __restrict__ Wsrel,
                             const float* __restrict__ Wvroot,
                             const float* __restrict__ Wvrel) {
    int i = blockIdx.x * blockDim.x + threadIdx.x;
    if (i < NN) { g_deg[i] = 0; g_cur[i] = 0; }
    if (i == 0) {
        int all_zero = 1;
        #pragma unroll
        for (int q = 0; q < 32; q++)
            if (ei32[2 * q + 1] != 0) all_zero = 0;
        g_is64 = all_zero;
    }
    if (i < 4 * HH * HH) {
        int m = i >> 14;
        int rest = i & (HH * HH - 1);
        int o = rest >> 7;
        int k = rest & 127;
        const float* src = (m == 0) ? Wsroot : (m == 1) ? Wsrel : (m == 2) ? Wvroot : Wvrel;
        g_Wt[(m << 14) + (k << 7) + o] = src[(o << 7) + k];
    }
}

// ---------------------------------------------------------------------------
// CSR build: histogram -> exclusive scan -> scatter (indices clamped).
__global__ void hist_kernel(const void* __restrict__ ei_raw) {
    int e = blockIdx.x * blockDim.x + threadIdx.x;
    if (e >= NE) return;
    int r = g_is64 ? (int)((const long long*)ei_raw)[e]
                   : ((const int*)ei_raw)[e];
    atomicAdd(&g_deg[clampn(r)], 1);
}

__global__ void scan_kernel() {
    __shared__ int sm[1024];
    int t = threadIdx.x;
    const int CH = (NN + 1023) / 1024;   // 49
    int b = t * CH;
    int e = min(b + CH, NN);
    int s = 0;
    for (int i = b; i < e; i++) s += g_deg[i];
    sm[t] = s;
    __syncthreads();
    for (int o = 1; o < 1024; o <<= 1) {
        int v = (t >= o) ? sm[t - o] : 0;
        __syncthreads();
        sm[t] += v;
        __syncthreads();
    }
    int run = (t == 0) ? 0 : sm[t - 1];
    for (int i = b; i < e; i++) { g_off[i] = run; run += g_deg[i]; }
    if (t == 1023) g_off[NN] = sm[1023];
}

__global__ void scatter_kernel(const void* __restrict__ ei_raw) {
    int e = blockIdx.x * blockDim.x + threadIdx.x;
    if (e >= NE) return;
    int r, c;
    if (g_is64) {
        const long long* ei = (const long long*)ei_raw;
        r = (int)ei[e];
        c = (int)ei[NE + e];
    } else {
        const int* ei = (const int*)ei_raw;
        r = ei[e];
        c = ei[NE + e];
    }
    r = clampn(r);
    c = clampn(c);
    int p = atomicAdd(&g_cur[r], 1);
    int slot = g_off[r] + p;
    if (slot >= NE) slot = NE - 1;
    g_ecol[slot] = c;
}

// ---------------------------------------------------------------------------
// Atomic-free gather aggregation (unchanged — proven).
#define GW 8
__global__ void gather_kernel(const float4* __restrict__ x4) {
    int w = threadIdx.x >> 5, lane = threadIdx.x & 31;
    const int ngb = NN / GW;            // 6250
    int bid = blockIdx.x;
    int pass = bid / ngb;
    int n = (bid - pass * ngb) * GW + w;
    int beg = g_off[n], end = g_off[n + 1];
    if (beg < 0) beg = 0;
    if (end > NE) end = NE;
    int jo = (pass << 5) + lane;

    float4 a0 = make_float4(0.f, 0.f, 0.f, 0.f);
    float4 a1 = a0;
    int i = beg;
    for (; i + 2 <= end; i += 2) {
        int c0 = g_ecol[i];
        int c1 = g_ecol[i + 1];
        float4 v0 = x4[(size_t)c0 * 128 + jo];
        float4 v1 = x4[(size_t)c1 * 128 + jo];
        a0.x += v0.x; a0.y += v0.y; a0.z += v0.z; a0.w += v0.w;
        a1.x += v1.x; a1.y += v1.y; a1.z += v1.z; a1.w += v1.w;
    }
    if (i < end) {
        int c0 = g_ecol[i];
        float4 v0 = x4[(size_t)c0 * 128 + jo];
        a0.x += v0.x; a0.y += v0.y; a0.z += v0.z; a0.w += v0.w;
    }
    float4 r = make_float4(a0.x + a1.x, a0.y + a1.y, a0.z + a1.z, a0.w + a1.w);
    ((float4*)g_agg)[(size_t)n * 128 + jo] = r;
}

// ---------------------------------------------------------------------------
// Fused GEMM: out_row = x_row @ Wroot^T + agg_row @ Wrel^T (+ b for scalar).
// Block: 128 rows x 128 outputs, 256 threads. Thread = 8 row-PAIRS x 4 outputs.
// Row-pairs come straight out of broadcast LDS.128 on the k-major A tile
// (ulonglong2 halves ARE the f32x2 operands — zero packing MOVs for A).
// W: 1 LDS.128 + 4 {w,w} dups per k (R5's proven amortization, now over 2x FLOPs).
__device__ __forceinline__ int rowbase(int is_s, int r, int mlim) {
    r = (r < mlim) ? r : (mlim - 1);
    if (is_s) return r << 9;
    int n = r / 3;
    int ch = r - n * 3;
    return (n << 9) + ((ch + 1) << 7);
}

#define TM 128
#define KT 32

__global__ __launch_bounds__(256, 2)
void gemm_kernel(const float* __restrict__ x,
                 const float* __restrict__ b_s,
                 float* __restrict__ out,
                 int nb_s) {
    __shared__ __align__(16) float As[KT][TM + 4];   // k-major; 528B stride (16B-multiple)
    __shared__ __align__(16) float Ws[KT][HH];       // [k][o]

    int t = threadIdx.x;
    int bid = (int)blockIdx.x;
    int is_s = (bid < nb_s) ? 1 : 0;
    int row0 = (is_s ? bid : bid - nb_s) * TM;
    int mlim = is_s ? NN : 3 * NN;
    const float* Wroot = g_Wt + (is_s ? 0 : 2 * HH * HH);
    const float* Wrel  = g_Wt + (is_s ? HH * HH : 3 * HH * HH);

    int ox = t & 31;        // output group: outputs ox*4 .. ox*4+3
    int ry = t >> 5;        // warp id: rows ry*16 .. ry*16+15 (A broadcast in warp)

    // A loader: thread -> row t>>1, k-half (t&1)*16 (16 floats)
    int alr = t >> 1;
    int akh = (t & 1) << 4;
    int ab = rowbase(is_s, row0 + alr, mlim);
    // W loader: 32 k-rows x 128 floats, thread copies 4 float4
    int wk = t >> 3;
    int wq = t & 7;

    ull acc[8][4];
    #pragma unroll
    for (int p = 0; p < 8; p++)
        #pragma unroll
        for (int j = 0; j < 4; j++) acc[p][j] = 0ULL;

    #pragma unroll 1
    for (int half = 0; half < 2; half++) {
        const float* A = half ? g_agg : x;
        const float* W = half ? Wrel : Wroot;
        #pragma unroll 1
        for (int kc = 0; kc < HH; kc += KT) {
            __syncthreads();
            // A tile: 128 rows x 32 k, stored k-major. 16 floats per thread.
            #pragma unroll
            for (int q4 = 0; q4 < 4; q4++) {
                float4 a = *(const float4*)(A + ab + kc + akh + q4 * 4);
                As[akh + q4 * 4 + 0][alr] = a.x;
                As[akh + q4 * 4 + 1][alr] = a.y;
                As[akh + q4 * 4 + 2][alr] = a.z;
                As[akh + q4 * 4 + 3][alr] = a.w;
            }
            // W tile copy (plain float, coalesced)
            {
                const float* wsrc = W + (size_t)(kc + wk) * HH;
                #pragma unroll
                for (int s = 0; s < 4; s++) {
                    float4 wv = *(const float4*)(wsrc + (wq + 8 * s) * 4);
                    *(float4*)(&Ws[wk][(wq + 8 * s) * 4]) = wv;
                }
            }
            __syncthreads();

            #pragma unroll
            for (int k = 0; k < KT; k++) {
                // 8 row-pairs via 4 broadcast LDS.128; halves are f32x2 operands
                ulonglong2 av[4];
                #pragma unroll
                for (int q = 0; q < 4; q++)
                    av[q] = *(const ulonglong2*)(&As[k][ry * 16 + q * 4]);
                float4 w = *(const float4*)(&Ws[k][ox * 4]);
                #pragma unroll
                for (int j = 0; j < 4; j++) {
                    float wj = (j == 0) ? w.x : (j == 1) ? w.y : (j == 2) ? w.z : w.w;
                    ull wp;
                    asm("mov.b64 %0, {%1, %1};" : "=l"(wp) : "f"(wj));
                    #pragma unroll
                    for (int q = 0; q < 4; q++) {
                        asm("fma.rn.f32x2 %0, %1, %2, %0;"
                            : "+l"(acc[2 * q][j]) : "l"(av[q].x), "l"(wp));
                        asm("fma.rn.f32x2 %0, %1, %2, %0;"
                            : "+l"(acc[2 * q + 1][j]) : "l"(av[q].y), "l"(wp));
                    }
                }
            }
        }
    }

    float4 bv = make_float4(0.f, 0.f, 0.f, 0.f);
    if (is_s) bv = *(const float4*)(b_s + ox * 4);

    #pragma unroll
    for (int p = 0; p < 8; p++) {
        int ra = row0 + ry * 16 + 2 * p;
        int rb = ra + 1;
        float lo[4], hi[4];
        #pragma unroll
        for (int j = 0; j < 4; j++)
            asm("mov.b64 {%0,%1}, %2;" : "=f"(lo[j]), "=f"(hi[j]) : "l"(acc[p][j]));
        if (ra < mlim) {
            float* dst = out + rowbase(is_s, ra, mlim) + ox * 4;
            *(float4*)dst = make_float4(lo[0] + bv.x, lo[1] + bv.y, lo[2] + bv.z, lo[3] + bv.w);
        }
        if (rb < mlim) {
            float* dst = out + rowbase(is_s, rb, mlim) + ox * 4;
            *(float4*)dst = make_float4(hi[0] + bv.x, hi[1] + bv.y, hi[2] + bv.z, hi[3] + bv.w);
        }
    }
}

// ---------------------------------------------------------------------------
extern "C" void kernel_launch(void* const* d_in, const int* in_sizes, int n_in,
                              void* d_out, int out_size) {
    const float* x      = (const float*)d_in[0];
    const void*  ei     = d_in[1];
    const float* Wsrel  = (const float*)d_in[2];
    const float* Wsroot = (const float*)d_in[3];
    const float* bsroot = (const float*)d_in[4];
    const float* Wvrel  = (const float*)d_in[5];
    const float* Wvroot = (const float*)d_in[6];
    float* out = (float*)d_out;

    setup_kernel<<<(4 * HH * HH + 255) / 256, 256>>>((const int*)ei, Wsroot, Wsrel, Wvroot, Wvrel);

    hist_kernel<<<(NE + 255) / 256, 256>>>(ei);
    scan_kernel<<<1, 1024>>>();
    scatter_kernel<<<(NE + 255) / 256, 256>>>(ei);

    gather_kernel<<<4 * (NN / GW), 256>>>((const float4*)x);

    int nb_s = (NN + TM - 1) / TM;            // 391
    int nb_v = (3 * NN + TM - 1) / TM;        // 1172
    gemm_kernel<<<nb_s + nb_v, 256>>>(x, bsroot, out, nb_s);
}